// round 8
// baseline (speedup 1.0000x reference)
#include <cuda_runtime.h>
#include <cstdint>

// Problem constants (fixed by the dataset)
#define BQ    128
#define TT    512
#define CC    1024
#define LL    64
#define SS    129           // 2*LL + 1 extended states
#define BLANKC 1023
#define EPSF  1e-7f
#define JPER  5             // states per lane (26 lanes * 5 = 130 >= 129)
#define NROWS 32            // smem ring rows (8 groups of 4)
#define RSTRIDE 68          // ring row stride in floats (66 used)
#define EF_TARGET 226       // rescale anchor: warp max near 2^99

__device__ __forceinline__ void cpasync4(uint32_t saddr, const float* g) {
    asm volatile("cp.async.ca.shared.global [%0], [%1], 4;" :: "r"(saddr), "l"(g));
}
__device__ __forceinline__ void cpcommit() {
    asm volatile("cp.async.commit_group;");
}
template <int N> __device__ __forceinline__ void cpwait() {
    asm volatile("cp.async.wait_group %0;" :: "n"(N));
}
// Non-aligned barrier (warps arrive from different code paths)
__device__ __forceinline__ void barsync() {
    asm volatile("barrier.sync 0;" ::: "memory");
}

__device__ __forceinline__ float pick5(const float a0, const float a1, const float a2,
                                       const float a3, const float a4, int j) {
    float r = a0;
    if (j == 1) r = a1;
    else if (j == 2) r = a2;
    else if (j == 3) r = a3;
    else if (j == 4) r = a4;
    return r;
}

__global__ __launch_bounds__(64, 1)
void ctc_ws_kernel(const int* __restrict__ y_true,
                   const float* __restrict__ y_pred,
                   const int* __restrict__ input_length,
                   const int* __restrict__ label_length,
                   float* __restrict__ out)
{
    __shared__ float ring[NROWS][RSTRIDE];

    const int b    = blockIdx.x;
    const int tid  = threadIdx.x;
    const int warp = tid >> 5;
    const int lane = tid & 31;
    const unsigned FULL = 0xffffffffu;

    const int Tb = input_length[b];          // block-uniform
    const int Ll = label_length[b];
    const int Sb = 2 * Ll + 1;
    const int NI = (Tb + 3) >> 2;            // 4-step groups

    const int*   lrow = y_true + b * LL;
    const float* prow = y_pred + (size_t)b * TT * CC;
    const uint32_t smem_base = (uint32_t)__cvta_generic_to_shared(&ring[0][0]);

    if (warp == 1) {
        // ================= PRODUCER =================
        const int lab0 = lrow[lane];
        const int lab1 = lrow[lane + 32];
        const int rmax = Tb < TT - 1 ? Tb : TT - 1;   // last row to fetch

        // prologue: groups 0..6 (rows 0..27)
#pragma unroll
        for (int g = 0; g < 7; g++) {
#pragma unroll
            for (int q = 0; q < 4; q++) {
                const int r = 4 * g + q;
                const float* pr = prow + (size_t)r * CC;
                const uint32_t wa = smem_base + (uint32_t)((r & (NROWS-1)) * RSTRIDE + lane) * 4u;
                cpasync4(wa, pr + lab0);
                cpasync4(wa + 128u, pr + lab1);
                if (lane == 0)
                    cpasync4(smem_base + (uint32_t)((r & (NROWS-1)) * RSTRIDE + 64) * 4u, pr + BLANKC);
            }
            cpcommit();
        }
        cpwait<5>();            // groups 0,1 complete (rows 0..7)
        barsync();              // S0

        for (int i = 0; i < NI; i++) {
            const int g = i + 7;
#pragma unroll
            for (int q = 0; q < 4; q++) {
                const int r = 4 * g + q;
                if (r <= rmax) {
                    const float* pr = prow + (size_t)r * CC;
                    const uint32_t wa = smem_base + (uint32_t)((r & (NROWS-1)) * RSTRIDE + lane) * 4u;
                    cpasync4(wa, pr + lab0);
                    cpasync4(wa + 128u, pr + lab1);
                    if (lane == 0)
                        cpasync4(smem_base + (uint32_t)((r & (NROWS-1)) * RSTRIDE + 64) * 4u, pr + BLANKC);
                }
            }
            cpcommit();
            cpwait<5>();        // complete through group i+1 (rows <= 4i+7)
            barsync();          // S(i+1)
        }
        cpwait<0>();            // drain before exit
    } else {
        // ================= CONSUMER =================
        // Per-lane static state metadata: states s = lane*5 + j
        int   off[JPER];
        float vsf[JPER], evf[JPER], skipf[JPER];
#pragma unroll
        for (int j = 0; j < JPER; j++) {
            const int s = lane * JPER + j;
            const bool v = (s < SS) && (s < Sb);
            int  o  = 64;                       // blank slot (sink for invalid too)
            bool sk = false;
            if (v && (s & 1)) {
                o = s >> 1;
                if (s >= 3) sk = (lrow[o] != lrow[o - 1]);
            }
            off[j]   = o;
            vsf[j]   = v ? 1.0f : 0.0f;
            evf[j]   = v ? EPSF : 0.0f;         // EPS * vsf
            skipf[j] = sk ? 1.0f : 0.0f;
        }

        float a0 = 0.f, a1r = 0.f, a2r = 0.f, a3r = 0.f, a4r = 0.f;
        if (lane == 0) a0 = 1.0f;

        barsync();              // S0: rows 0..7 resident

        // ee[parity][j]: emissions for current / next step
        float ee[2][JPER];
#pragma unroll
        for (int j = 0; j < JPER; j++)
            ee[0][j] = fmaf(ring[0][off[j]], vsf[j], evf[j]);

        int esum = 0;           // exact power-of-two rescale accumulator

        for (int i = 0; i < NI; i++) {
#pragma unroll
            for (int k = 0; k < 4; k++) {
                const int t   = 4 * i + k;
                const int cur = t & 1;
                const int nxt = cur ^ 1;

                // read raw emissions for step t+1 (resident per barrier contract)
                const int tn = (t + 1 < TT) ? (t + 1) : (TT - 1);
                const float* rr = &ring[tn & (NROWS - 1)][0];
                float r0 = rr[off[0]], r1 = rr[off[1]], r2 = rr[off[2]],
                      r3 = rr[off[3]], r4 = rr[off[4]];

                if (t < Tb) {
                    float h3 = __shfl_up_sync(FULL, a3r, 1);
                    float h4 = __shfl_up_sync(FULL, a4r, 1);
                    if (lane == 0) { h3 = 0.f; h4 = 0.f; }

                    const float n0 = (a0  + h4  + skipf[0] * h3 ) * ee[cur][0];
                    const float n1 = (a1r + a0  + skipf[1] * h4 ) * ee[cur][1];
                    const float n2 = (a2r + a1r + skipf[2] * a0 ) * ee[cur][2];
                    const float n3 = (a3r + a2r + skipf[3] * a1r) * ee[cur][3];
                    const float n4 = (a4r + a3r + skipf[4] * a2r) * ee[cur][4];
                    a0 = n0; a1r = n1; a2r = n2; a3r = n3; a4r = n4;
                }

                // build emissions for step t+1 (one FFMA per state)
                ee[nxt][0] = fmaf(r0, vsf[0], evf[0]);
                ee[nxt][1] = fmaf(r1, vsf[1], evf[1]);
                ee[nxt][2] = fmaf(r2, vsf[2], evf[2]);
                ee[nxt][3] = fmaf(r3, vsf[3], evf[3]);
                ee[nxt][4] = fmaf(r4, vsf[4], evf[4]);

                // exact power-of-two rescale every 4 steps (applied to alphas)
                if (k == 3 && t < Tb) {
                    float m = fmaxf(fmaxf(fmaxf(a0, a1r), fmaxf(a2r, a3r)), a4r);
                    unsigned mu = __reduce_max_sync(FULL, __float_as_uint(m));
                    if (mu != 0u) {
                        const int ef = (int)(mu >> 23);
                        int kk = EF_TARGET - ef;
                        kk = kk > 127 ? 127 : (kk < -126 ? -126 : kk);
                        const float sc = __int_as_float((unsigned)(127 + kk) << 23); // 2^kk
                        esum -= kk;
                        a0 *= sc; a1r *= sc; a2r *= sc; a3r *= sc; a4r *= sc;
                    }
                }
            }
            barsync();          // S(i+1)
        }

        // loss = -( log(alpha[2Ll] + alpha[2Ll-1]) + esum*ln2 )
        const int se0 = 2 * Ll;
        const int se1 = 2 * Ll - 1;
        const int l0 = se0 / JPER, j0 = se0 % JPER;
        const int l1 = se1 / JPER, j1 = se1 % JPER;

        const float v0 = pick5(a0, a1r, a2r, a3r, a4r, j0);
        const float v1 = pick5(a0, a1r, a2r, a3r, a4r, j1);
        const float fa1 = __shfl_sync(FULL, v0, l0);
        const float fa2 = __shfl_sync(FULL, v1, l1);

        if (lane == 0) {
            const float s = fmaxf(fa1 + fa2, 1e-43f);
            out[b] = -(logf(s) + (float)esum * 0.6931471805599453f);
        }
    }
}

extern "C" void kernel_launch(void* const* d_in, const int* in_sizes, int n_in,
                              void* d_out, int out_size)
{
    const int*   y_true       = (const int*)  d_in[0];   // [B,L] int32
    const float* y_pred       = (const float*)d_in[1];   // [B,T,C] f32
    const int*   input_length = (const int*)  d_in[2];   // [B,1] int32
    const int*   label_length = (const int*)  d_in[3];   // [B,1] int32
    float*       out          = (float*)d_out;           // [B,1] f32

    ctc_ws_kernel<<<BQ, 64>>>(y_true, y_pred, input_length, label_length, out);
}